// round 6
// baseline (speedup 1.0000x reference)
#include <cuda_runtime.h>
#include <cuda_bf16.h>

// Retrace: per-(b,d) reverse affine scan + MSE reduction.
// Shapes: B=2048, T=512, D=16. fp32. Output: 1 fp32 scalar.
// Segment-parallel affine scan (q = P*x + S per 64-step segment; MSE quadratic
// in carry-in x). float2 loads (lane = 2 adjacent d), __ldcs streaming,
// warp = 4 b-rows x 8 d-pairs. R4: unroll 2 + launch_bounds(256,4) to cap
// regs at 64 -> 4 resident blocks/SM (R3's 78 regs allowed only 3).

#define RB 2048
#define RT 512
#define RD 16
#define NSEG 8
#define SEGLEN 64
#define CHAINS_PER_BLK 64     // 32 lanes x 2 chains
#define GAMMA 0.99f

__global__ __launch_bounds__(256, 4)
void retrace_seg2_kernel(const float* __restrict__ Q,
                         const float* __restrict__ eQ,
                         const float* __restrict__ tQ,
                         const float* __restrict__ rw,
                         const float* __restrict__ tpp,
                         const float* __restrict__ bpp,
                         float* __restrict__ out)
{
    const int lane = threadIdx.x & 31;
    const int seg  = threadIdx.x >> 5;          // time segment 0..7
    const int b_off = lane >> 3;                // 0..3
    const int d2    = (lane & 7) * 2;           // 0,2,..,14
    const int b = blockIdx.x * 4 + b_off;

    const size_t base = (size_t)b * (RT * RD) + d2;     // float index
    const float2* q_p   = (const float2*)(Q   + base);
    const float2* e_p   = (const float2*)(eQ  + base);
    const float2* tq_p  = (const float2*)(tQ  + base);
    const float2* r_p   = (const float2*)(rw  + base);
    const float2* tpp_p = (const float2*)(tpp + base);
    const float*  bpp_p = bpp + (size_t)b * RT;
    const int RD2 = RD / 2;                      // float2 stride per t

    const int lo = seg * SEGLEN;
    const int hi = (seg == NSEG - 1) ? (RT - 2) : (lo + SEGLEN - 1);

    // two independent chains per lane
    float P0 = 1.0f, S0 = 0.0f, D20 = 0.0f, DP0 = 0.0f, P20 = 0.0f;
    float P1 = 1.0f, S1 = 0.0f, D21 = 0.0f, DP1 = 0.0f, P21 = 0.0f;

    #pragma unroll 2
    for (int t = hi; t >= lo; --t) {
        const int j = t + 1;
        float  lb = __ldg(bpp_p + j);
        float2 lt = __ldcs(tpp_p + j * RD2);
        float2 le = __ldcs(e_p   + j * RD2);
        float2 lq = __ldcs(tq_p  + j * RD2);
        float2 lr = __ldcs(r_p   + t * RD2);
        float2 lQ = __ldcs(q_p   + t * RD2);

        float gc0 = GAMMA * __expf(fminf(lt.x - lb, 0.0f));
        float gc1 = GAMMA * __expf(fminf(lt.y - lb, 0.0f));

        float bse0 = fmaf(GAMMA, le.x, lr.x); bse0 = fmaf(-gc0, lq.x, bse0);
        float bse1 = fmaf(GAMMA, le.y, lr.y); bse1 = fmaf(-gc1, lq.y, bse1);

        P0 = gc0 * P0;  S0 = fmaf(gc0, S0, bse0);
        P1 = gc1 * P1;  S1 = fmaf(gc1, S1, bse1);

        float dv0 = lQ.x - S0;
        float dv1 = lQ.y - S1;
        D20 = fmaf(dv0, dv0, D20);  DP0 = fmaf(dv0, P0, DP0);  P20 = fmaf(P0, P0, P20);
        D21 = fmaf(dv1, dv1, D21);  DP1 = fmaf(dv1, P1, DP1);  P21 = fmaf(P1, P1, P21);
    }

    __shared__ float shA [NSEG][CHAINS_PER_BLK];
    __shared__ float shB [NSEG][CHAINS_PER_BLK];
    __shared__ float shD2[NSEG][CHAINS_PER_BLK];
    __shared__ float shDP[NSEG][CHAINS_PER_BLK];
    __shared__ float shP2[NSEG][CHAINS_PER_BLK];
    const int c0 = lane * 2, c1 = c0 + 1;
    shA [seg][c0] = P0;  shA [seg][c1] = P1;
    shB [seg][c0] = S0;  shB [seg][c1] = S1;
    shD2[seg][c0] = D20; shD2[seg][c1] = D21;
    shDP[seg][c0] = DP0; shDP[seg][c1] = DP1;
    shP2[seg][c0] = P20; shP2[seg][c1] = P21;
    __syncthreads();

    // warp 0 combines: each lane handles its own 2 chains (same c0/c1 mapping)
    if (seg == 0) {
        float2 x2 = __ldg(tq_p + (RT - 1) * RD2);  // carry init = target_Q[:, -1]
        float acc = 0.0f;
        float x0 = x2.x, x1 = x2.y;
        #pragma unroll
        for (int s = NSEG - 1; s >= 0; --s) {
            acc += fmaf(x0, fmaf(x0, shP2[s][c0], -2.0f * shDP[s][c0]), shD2[s][c0]);
            acc += fmaf(x1, fmaf(x1, shP2[s][c1], -2.0f * shDP[s][c1]), shD2[s][c1]);
            x0 = fmaf(shA[s][c0], x0, shB[s][c0]);
            x1 = fmaf(shA[s][c1], x1, shB[s][c1]);
        }
        const float inv_n = 1.0f / (float)((size_t)RB * (RT - 1) * RD);
        acc *= inv_n;

        #pragma unroll
        for (int off = 16; off > 0; off >>= 1)
            acc += __shfl_down_sync(0xFFFFFFFFu, acc, off);
        if (lane == 0)
            atomicAdd(out, acc);
    }
}

extern "C" void kernel_launch(void* const* d_in, const int* in_sizes, int n_in,
                              void* d_out, int out_size)
{
    const float* Q   = (const float*)d_in[0];
    const float* eQ  = (const float*)d_in[1];
    const float* tQ  = (const float*)d_in[2];
    const float* rw  = (const float*)d_in[3];
    const float* tpp = (const float*)d_in[4];
    const float* bpp = (const float*)d_in[5];
    float* out = (float*)d_out;

    cudaMemsetAsync(out, 0, sizeof(float), 0);

    const int blocks = (RB * RD) / CHAINS_PER_BLK;   // 512
    retrace_seg2_kernel<<<blocks, NSEG * 32>>>(Q, eQ, tQ, rw, tpp, bpp, out);
}

// round 9
// speedup vs baseline: 1.2139x; 1.2139x over previous
#include <cuda_runtime.h>
#include <cuda_bf16.h>

// Retrace: per-(b,d) reverse affine scan + MSE reduction.
// Shapes: B=2048, T=512, D=16. All inputs fp32. Output: 1 fp32 scalar.
// Segment-parallel: q_t = gc_t * q_{t+1} + base_t is affine in the carry, so
// each 64-step segment reduces to (P, S) with q = P*x + S, and its squared-error
// contribution is quadratic in x: sumD2 - 2x*sumDP + x^2*sumP2.
// Block = 32 chains x 8 segments (warp = segment, lane = chain).
// R6: identical to the 61.5us R2 kernel except unroll 4 -> 8 (more LDGs in
// flight per thread) with launch_bounds(256,4) pinning regs at <=64.

#define RB 2048
#define RT 512
#define RD 16
#define NSEG 8
#define SEGLEN 64
#define CHAINS_PER_BLK 32
#define GAMMA 0.99f

__global__ __launch_bounds__(256, 4)
void retrace_seg_kernel(const float* __restrict__ Q,
                        const float* __restrict__ eQ,
                        const float* __restrict__ tQ,
                        const float* __restrict__ rw,
                        const float* __restrict__ tpp,
                        const float* __restrict__ bpp,
                        float* __restrict__ out)
{
    const int lane = threadIdx.x & 31;       // chain within block
    const int seg  = threadIdx.x >> 5;       // time segment 0..7
    const int chain = blockIdx.x * CHAINS_PER_BLK + lane;  // 0 .. B*D-1
    const int b = chain >> 4;                // D = 16
    const int d = chain & 15;

    const size_t base = (size_t)b * (RT * RD) + d;
    const float* q_p   = Q   + base;
    const float* e_p   = eQ  + base;
    const float* tq_p  = tQ  + base;
    const float* r_p   = rw  + base;
    const float* tpp_p = tpp + base;
    const float* bpp_p = bpp + (size_t)b * RT;

    const int lo = seg * SEGLEN;
    const int hi = (seg == NSEG - 1) ? (RT - 2) : (lo + SEGLEN - 1);

    // Backward scan within segment: q = P*x + S (x = carry entering at t=hi+1)
    float P = 1.0f, S = 0.0f;
    float sumD2 = 0.0f, sumDP = 0.0f, sumP2 = 0.0f;

    #pragma unroll 8
    for (int t = hi; t >= lo; --t) {
        const int j = t + 1;
        float lw  = tpp_p[j * RD] - bpp_p[j];
        float gc  = GAMMA * __expf(fminf(lw, 0.0f));
        float bse = fmaf(GAMMA, e_p[j * RD], r_p[t * RD]);
        bse       = fmaf(-gc, tq_p[j * RD], bse);
        P = gc * P;
        S = fmaf(gc, S, bse);
        float dv = q_p[t * RD] - S;          // diff = dv - P*x
        sumD2 = fmaf(dv, dv, sumD2);
        sumDP = fmaf(dv, P,  sumDP);
        sumP2 = fmaf(P,  P,  sumP2);
    }

    __shared__ float shA [NSEG][CHAINS_PER_BLK];
    __shared__ float shB [NSEG][CHAINS_PER_BLK];
    __shared__ float shD2[NSEG][CHAINS_PER_BLK];
    __shared__ float shDP[NSEG][CHAINS_PER_BLK];
    __shared__ float shP2[NSEG][CHAINS_PER_BLK];
    shA [seg][lane] = P;
    shB [seg][lane] = S;
    shD2[seg][lane] = sumD2;
    shDP[seg][lane] = sumDP;
    shP2[seg][lane] = sumP2;
    __syncthreads();

    // Warp 0: serial combine over 8 segments for each of the 32 chains.
    if (seg == 0) {
        float x = tq_p[(RT - 1) * RD];       // initial carry = target_Q[:, -1]
        float acc = 0.0f;
        #pragma unroll
        for (int s = NSEG - 1; s >= 0; --s) {
            float a2 = shD2[s][lane], dp = shDP[s][lane], p2 = shP2[s][lane];
            acc += fmaf(x, fmaf(x, p2, -2.0f * dp), a2);
            x = fmaf(shA[s][lane], x, shB[s][lane]);
        }
        const float inv_n = 1.0f / (float)((size_t)RB * (RT - 1) * RD);
        acc *= inv_n;

        #pragma unroll
        for (int off = 16; off > 0; off >>= 1)
            acc += __shfl_down_sync(0xFFFFFFFFu, acc, off);
        if (lane == 0)
            atomicAdd(out, acc);
    }
}

extern "C" void kernel_launch(void* const* d_in, const int* in_sizes, int n_in,
                              void* d_out, int out_size)
{
    const float* Q   = (const float*)d_in[0];
    const float* eQ  = (const float*)d_in[1];
    const float* tQ  = (const float*)d_in[2];
    const float* rw  = (const float*)d_in[3];
    const float* tpp = (const float*)d_in[4];
    const float* bpp = (const float*)d_in[5];
    float* out = (float*)d_out;

    cudaMemsetAsync(out, 0, sizeof(float), 0);

    const int blocks = (RB * RD) / CHAINS_PER_BLK;   // 1024
    retrace_seg_kernel<<<blocks, NSEG * 32>>>(Q, eQ, tQ, rw, tpp, bpp, out);
}

// round 10
// speedup vs baseline: 1.3780x; 1.1352x over previous
#include <cuda_runtime.h>
#include <cuda_bf16.h>

// Retrace: per-(b,d) reverse affine scan + MSE reduction.
// Shapes: B=2048, T=512, D=16. All inputs fp32. Output: 1 fp32 scalar.
// Segment-parallel: q_t = gc_t * q_{t+1} + base_t is affine in the carry, so
// each segment reduces to (P, S) with q = P*x + S, and its squared-error
// contribution is quadratic in x: sumD2 - 2x*sumDP + x^2*sumP2.
// R9: NSEG 8 -> 16 (SEGLEN 32), block 512 (warp = segment, lane = chain).
// Inner loop identical to the 61.5us R2 kernel (unroll 4, scalar LDG).
// 56 regs x 512 thr -> 2 resident blocks/SM = 32 warps (50% occ) vs 28.

#define RB 2048
#define RT 512
#define RD 16
#define NSEG 16
#define SEGLEN 32
#define CHAINS_PER_BLK 32
#define GAMMA 0.99f

__global__ __launch_bounds__(512, 2)
void retrace_seg_kernel(const float* __restrict__ Q,
                        const float* __restrict__ eQ,
                        const float* __restrict__ tQ,
                        const float* __restrict__ rw,
                        const float* __restrict__ tpp,
                        const float* __restrict__ bpp,
                        float* __restrict__ out)
{
    const int lane = threadIdx.x & 31;       // chain within block
    const int seg  = threadIdx.x >> 5;       // time segment 0..15
    const int chain = blockIdx.x * CHAINS_PER_BLK + lane;  // 0 .. B*D-1
    const int b = chain >> 4;                // D = 16
    const int d = chain & 15;

    const size_t base = (size_t)b * (RT * RD) + d;
    const float* q_p   = Q   + base;
    const float* e_p   = eQ  + base;
    const float* tq_p  = tQ  + base;
    const float* r_p   = rw  + base;
    const float* tpp_p = tpp + base;
    const float* bpp_p = bpp + (size_t)b * RT;

    const int lo = seg * SEGLEN;
    const int hi = (seg == NSEG - 1) ? (RT - 2) : (lo + SEGLEN - 1);

    // Backward scan within segment: q = P*x + S (x = carry entering at t=hi+1)
    float P = 1.0f, S = 0.0f;
    float sumD2 = 0.0f, sumDP = 0.0f, sumP2 = 0.0f;

    #pragma unroll 4
    for (int t = hi; t >= lo; --t) {
        const int j = t + 1;
        float lw  = tpp_p[j * RD] - bpp_p[j];
        float gc  = GAMMA * __expf(fminf(lw, 0.0f));
        float bse = fmaf(GAMMA, e_p[j * RD], r_p[t * RD]);
        bse       = fmaf(-gc, tq_p[j * RD], bse);
        P = gc * P;
        S = fmaf(gc, S, bse);
        float dv = q_p[t * RD] - S;          // diff = dv - P*x
        sumD2 = fmaf(dv, dv, sumD2);
        sumDP = fmaf(dv, P,  sumDP);
        sumP2 = fmaf(P,  P,  sumP2);
    }

    __shared__ float shA [NSEG][CHAINS_PER_BLK];
    __shared__ float shB [NSEG][CHAINS_PER_BLK];
    __shared__ float shD2[NSEG][CHAINS_PER_BLK];
    __shared__ float shDP[NSEG][CHAINS_PER_BLK];
    __shared__ float shP2[NSEG][CHAINS_PER_BLK];
    shA [seg][lane] = P;
    shB [seg][lane] = S;
    shD2[seg][lane] = sumD2;
    shDP[seg][lane] = sumDP;
    shP2[seg][lane] = sumP2;
    __syncthreads();

    // Warp 0: serial combine over 16 segments for each of the 32 chains.
    if (seg == 0) {
        float x = tq_p[(RT - 1) * RD];       // initial carry = target_Q[:, -1]
        float acc = 0.0f;
        #pragma unroll
        for (int s = NSEG - 1; s >= 0; --s) {
            float a2 = shD2[s][lane], dp = shDP[s][lane], p2 = shP2[s][lane];
            acc += fmaf(x, fmaf(x, p2, -2.0f * dp), a2);
            x = fmaf(shA[s][lane], x, shB[s][lane]);
        }
        const float inv_n = 1.0f / (float)((size_t)RB * (RT - 1) * RD);
        acc *= inv_n;

        #pragma unroll
        for (int off = 16; off > 0; off >>= 1)
            acc += __shfl_down_sync(0xFFFFFFFFu, acc, off);
        if (lane == 0)
            atomicAdd(out, acc);
    }
}

extern "C" void kernel_launch(void* const* d_in, const int* in_sizes, int n_in,
                              void* d_out, int out_size)
{
    const float* Q   = (const float*)d_in[0];
    const float* eQ  = (const float*)d_in[1];
    const float* tQ  = (const float*)d_in[2];
    const float* rw  = (const float*)d_in[3];
    const float* tpp = (const float*)d_in[4];
    const float* bpp = (const float*)d_in[5];
    float* out = (float*)d_out;

    cudaMemsetAsync(out, 0, sizeof(float), 0);

    const int blocks = (RB * RD) / CHAINS_PER_BLK;   // 1024
    retrace_seg_kernel<<<blocks, NSEG * 32>>>(Q, eQ, tQ, rw, tpp, bpp, out);
}